// round 14
// baseline (speedup 1.0000x reference)
#include <cuda_runtime.h>
#include <cuda_bf16.h>
#include <cstdint>

// Problem constants: B=4, T=32 -> BT=128 slices; N=512 nodes; F_in=D=128.
#define BT    128
#define NN    512
#define DD    128
#define NROWS (BT * NN)       // 65536 total node-rows

typedef unsigned long long u64;
typedef unsigned int       u32;
typedef unsigned short     u16;

// Scratch (allocation-free: __device__ globals)
__device__ float g_es[NROWS], g_ed[NROWS];
__device__ float g_F[NROWS], g_f[NROWS];           // exp(es), exp(0.2*es)
__device__ float g_G[NROWS], g_g[NROWS];           // exp(ed), exp(0.2*ed)
__device__ unsigned g_adjbits[NN * 16];            // bit j%32 of word [i][j/32]
// Wh transposed per slice, split into bf16 hi/lo: index [(bt*128 + d)*512 + j]
__device__ __align__(16) __nv_bfloat16 g_WhT_hi[NROWS * DD];
__device__ __align__(16) __nv_bfloat16 g_WhT_lo[NROWS * DD];

// ---- f32x2 helpers (k_gemm mainloop only) ----
__device__ __forceinline__ u64 pack2(float lo, float hi) {
    u64 r; asm("mov.b64 %0, {%1, %2};" : "=l"(r) : "f"(lo), "f"(hi)); return r;
}
__device__ __forceinline__ void ffma2(u64& d, u64 a, u64 b) {
    asm("fma.rn.f32x2 %0, %1, %2, %0;" : "+l"(d) : "l"(a), "l"(b));
}
__device__ __forceinline__ float2 unpack2(u64 v) {
    float2 f; asm("mov.b64 {%0, %1}, %2;" : "=f"(f.x), "=f"(f.y) : "l"(v)); return f;
}

__device__ __forceinline__ u32 smem_u32(const void* p) {
    u32 a;
    asm("{ .reg .u64 t; cvta.to.shared.u64 t, %1; cvt.u32.u64 %0, t; }"
        : "=r"(a) : "l"(p));
    return a;
}

// ---- family-portable tensor ops: ldmatrix + mma.sync (bf16, f32 acc) ----
#define LDSM4(r, addr) \
    asm volatile("ldmatrix.sync.aligned.m8n8.x4.shared.b16 {%0,%1,%2,%3}, [%4];" \
        : "=r"((r)[0]), "=r"((r)[1]), "=r"((r)[2]), "=r"((r)[3]) : "r"(addr))

__device__ __forceinline__ void mma_bf16(float* d, const u32* a, const u32* b) {
    asm volatile("mma.sync.aligned.m16n8k16.row.col.f32.bf16.bf16.f32 "
        "{%0,%1,%2,%3}, {%4,%5,%6,%7}, {%8,%9}, {%0,%1,%2,%3};"
        : "+f"(d[0]), "+f"(d[1]), "+f"(d[2]), "+f"(d[3])
        : "r"(a[0]), "r"(a[1]), "r"(a[2]), "r"(a[3]), "r"(b[0]), "r"(b[1]));
}

// ---------------------------------------------------------------------------
// Kernel 1: Wh = h @ W  (M=65536, K=128, N=128), tile 64x128.
// Epilogue: es/ed dot products + exp tables + smem-staged TRANSPOSED bf16
// hi/lo Wh store (coalesced STG.128 instead of scattered STG.16).
// ---------------------------------------------------------------------------
#define TBP 130                          // transpose buffer pitch (bf16), odd u32
__global__ __launch_bounds__(256) void k_gemm(const float* __restrict__ h,
                                              const float* __restrict__ W,
                                              const float* __restrict__ a) {
    __shared__ union {
        struct { float hs[64][33]; float Ws[32][128]; } mm;   // 24832 B
        __nv_bfloat16 tb[2][64 * TBP];                        // 33280 B
    } sm;
    __shared__ float sred[64][17];
    __shared__ float dred[64][17];

    const int row0 = blockIdx.x * 64;
    const int tid  = threadIdx.x;
    const int tx   = tid & 15;
    const int ty   = tid >> 4;

    u64 acc2[4][4];
#pragma unroll
    for (int r = 0; r < 4; r++)
#pragma unroll
        for (int d = 0; d < 4; d++) acc2[r][d] = 0ull;

    for (int k0 = 0; k0 < 128; k0 += 32) {
        __syncthreads();
#pragma unroll
        for (int l = 0; l < 2; l++) {
            int idx = tid + l * 256;
            int r = idx >> 3, c4 = (idx & 7) * 4;
            float4 v = *(const float4*)&h[(size_t)(row0 + r) * 128 + k0 + c4];
            sm.mm.hs[r][c4 + 0] = v.x; sm.mm.hs[r][c4 + 1] = v.y;
            sm.mm.hs[r][c4 + 2] = v.z; sm.mm.hs[r][c4 + 3] = v.w;
        }
#pragma unroll
        for (int l = 0; l < 4; l++) {
            int idx = tid + l * 256;
            int kk = idx >> 5, dc = (idx & 31) * 4;
            *(float4*)&sm.mm.Ws[kk][dc] = *(const float4*)&W[(k0 + kk) * 128 + dc];
        }
        __syncthreads();
#pragma unroll 8
        for (int k = 0; k < 32; k++) {
            ulonglong2 wa = *(const ulonglong2*)&sm.mm.Ws[k][tx * 8];
            ulonglong2 wb = *(const ulonglong2*)&sm.mm.Ws[k][tx * 8 + 4];
#pragma unroll
            for (int r = 0; r < 4; r++) {
                float hv = sm.mm.hs[ty + r * 16][k];
                u64 h2 = pack2(hv, hv);
                ffma2(acc2[r][0], h2, wa.x);
                ffma2(acc2[r][1], h2, wa.y);
                ffma2(acc2[r][2], h2, wb.x);
                ffma2(acc2[r][3], h2, wb.y);
            }
        }
    }
    __syncthreads();   // mainloop reads of hs/Ws done before tb overwrite

    float a_s[8], a_d[8];
#pragma unroll
    for (int d = 0; d < 8; d++) {
        a_s[d] = a[tx * 8 + d];
        a_d[d] = a[128 + tx * 8 + d];
    }

#pragma unroll
    for (int r = 0; r < 4; r++) {
        int rl = ty + r * 16;              // local j (0..63)
        float v[8];
        float2 p;
        p = unpack2(acc2[r][0]); v[0] = p.x; v[1] = p.y;
        p = unpack2(acc2[r][1]); v[2] = p.x; v[3] = p.y;
        p = unpack2(acc2[r][2]); v[4] = p.x; v[5] = p.y;
        p = unpack2(acc2[r][3]); v[6] = p.x; v[7] = p.y;
        float s = 0.f, dd = 0.f;
#pragma unroll
        for (int d = 0; d < 8; d += 2) {
            s  += v[d] * a_s[d]     + v[d + 1] * a_s[d + 1];
            dd += v[d] * a_d[d]     + v[d + 1] * a_d[d + 1];
            __nv_bfloat162 hp = __floats2bfloat162_rn(v[d], v[d + 1]);
            float l0 = v[d]     - __bfloat162float(hp.x);
            float l1 = v[d + 1] - __bfloat162float(hp.y);
            __nv_bfloat162 lp = __floats2bfloat162_rn(l0, l1);
            *(u32*)&sm.tb[0][rl * TBP + tx * 8 + d] = *(u32*)&hp;
            *(u32*)&sm.tb[1][rl * TBP + tx * 8 + d] = *(u32*)&lp;
        }
        sred[rl][tx] = s;
        dred[rl][tx] = dd;
    }
    __syncthreads();

    // es/ed reduction + exp tables
    if (tid < 64) {
        float s = 0.f, dd = 0.f;
#pragma unroll
        for (int t = 0; t < 16; t++) { s += sred[tid][t]; dd += dred[tid][t]; }
        int n = row0 + tid;
        g_es[n] = s;  g_ed[n] = dd;
        g_F[n] = expf(s);         g_f[n] = expf(0.2f * s);
        g_G[n] = expf(dd);        g_g[n] = expf(0.2f * dd);
    }

    // transposed coalesced store: thread = d-row (tid>>1), j-half (tid&1)
    {
        const int bts   = row0 >> 9;
        const int jcol0 = row0 & 511;
        const int dr    = tid >> 1;
        const int jb    = (tid & 1) * 32;
        size_t gbase = ((size_t)bts * 128 + dr) * 512 + jcol0 + jb;
#pragma unroll
        for (int buf = 0; buf < 2; buf++) {
            __nv_bfloat16* gdst = buf ? g_WhT_lo : g_WhT_hi;
            const __nv_bfloat16* src = sm.tb[buf];
#pragma unroll
            for (int q = 0; q < 4; q++) {
                u16 w[8];
#pragma unroll
                for (int e = 0; e < 8; e++)
                    w[e] = *(const u16*)&src[(jb + q * 8 + e) * TBP + dr];
                *(uint4*)&gdst[gbase + q * 8] = *(uint4*)w;
            }
        }
    }
}

// ---------------------------------------------------------------------------
// Kernel 2: adjacency -> bitmask
// ---------------------------------------------------------------------------
__global__ __launch_bounds__(256) void k_adjbits(const int* __restrict__ adj) {
    int idx = blockIdx.x * 256 + threadIdx.x;
    int i = idx >> 4, w = idx & 15;
    unsigned bits = 0;
#pragma unroll
    for (int b = 0; b < 32; b++)
        if (adj[i * NN + w * 32 + b] > 0) bits |= (1u << b);
    g_adjbits[idx] = bits;
}

// ---------------------------------------------------------------------------
// Kernel 3: tensor-core (mma.sync bf16) fused masked-softmax-attention.
// D[d][i] = sum_j WhT[d][j] * C[i][j];  out[i][d] = D[d][i] / den[i]
// (unchanged from R10 passing version)
// ---------------------------------------------------------------------------
#define PITCH_B 144                      // 72 bf16 per row
__global__ __launch_bounds__(256) void k_attn(float* __restrict__ out) {
    extern __shared__ char dyn[];
    char* smA_hi = dyn;                  // [128][72] bf16 = 18432 B
    char* smA_lo = dyn + 18432;
    char* smB_hi = dyn + 36864;
    char* smB_lo = dyn + 55296;          // total 73728 B

    __shared__ unsigned bitsS[128 * 16];
    __shared__ float edS[64], GS[64], gS[64];
    __shared__ float denS[256];
    __shared__ float invD[128];

    const int tid  = threadIdx.x;
    const int lane = tid & 31;
    const int wp   = tid >> 5;
    const int bt   = blockIdx.x >> 2;
    const int tile = blockIdx.x & 3;
    const int base = bt * NN;
    const int i0   = tile * 128;

#pragma unroll
    for (int l = 0; l < 2; l++) {
        int idx4 = tid + l * 256;
        int r = idx4 >> 2, w4 = (idx4 & 3) * 4;
        *(uint4*)&bitsS[r * 16 + w4] = *(const uint4*)&g_adjbits[(i0 + r) * 16 + w4];
    }

    const int i    = tid >> 1;
    const int half = tid & 1;
    const float esv = g_es[base + i0 + i];
    const float Fv  = g_F[base + i0 + i];
    const float fv  = g_f[base + i0 + i];
    float den = 0.f;

    const __nv_bfloat16* srcHi = g_WhT_hi + (size_t)bt * 128 * 512;
    const __nv_bfloat16* srcLo = g_WhT_lo + (size_t)bt * 128 * 512;

    const int arow  = (lane & 7) + ((lane >> 3) & 1) * 8;
    const int akoff = (lane >> 4) * 8;
    const int brow  = (lane & 7) + (lane >> 4) * 8;
    const int bkoff = ((lane >> 3) & 1) * 8;
    const u32 adAhi = smem_u32(smA_hi) + (wp * 16 + arow) * PITCH_B + akoff * 2;
    const u32 adAlo = smem_u32(smA_lo) + (wp * 16 + arow) * PITCH_B + akoff * 2;
    const u32 adBhi = smem_u32(smB_hi) + brow * PITCH_B + bkoff * 2;
    const u32 adBlo = smem_u32(smB_lo) + brow * PITCH_B + bkoff * 2;

    float acc[16][4];
#pragma unroll
    for (int nf = 0; nf < 16; nf++)
#pragma unroll
        for (int q = 0; q < 4; q++) acc[nf][q] = 0.f;

    for (int ch = 0; ch < 8; ch++) {
        const int j0 = ch * 64;
        __syncthreads();
        if (tid < 64)       edS[tid]      = g_ed[base + j0 + tid];
        else if (tid < 128) GS[tid - 64]  = g_G[base + j0 + tid - 64];
        else if (tid < 192) gS[tid - 128] = g_g[base + j0 + tid - 128];
        {
            const int slot = tid & 7;
            const int drow = tid >> 3;
#pragma unroll
            for (int it = 0; it < 4; it++) {
                int d = drow + it * 32;
                size_t off = (size_t)d * 512 + j0 + slot * 8;
                *(uint4*)(smA_hi + d * PITCH_B + slot * 16) = *(const uint4*)(srcHi + off);
                *(uint4*)(smA_lo + d * PITCH_B + slot * 16) = *(const uint4*)(srcLo + off);
            }
        }
        __syncthreads();
        {
            unsigned bits = bitsS[i * 16 + ch * 2 + half];
#pragma unroll
            for (int jj = 0; jj < 32; jj += 2) {
                int j = half * 32 + jj;
                float c0 = 0.f, c1 = 0.f;
                if ((bits >> jj) & 1u) {
                    float t = esv + edS[j];
                    c0 = (t > 0.f) ? Fv * GS[j] : fv * gS[j];
                }
                if ((bits >> (jj + 1)) & 1u) {
                    float t = esv + edS[j + 1];
                    c1 = (t > 0.f) ? Fv * GS[j + 1] : fv * gS[j + 1];
                }
                den += c0 + c1;
                __nv_bfloat162 hp = __floats2bfloat162_rn(c0, c1);
                float l0 = c0 - __bfloat162float(hp.x);
                float l1 = c1 - __bfloat162float(hp.y);
                __nv_bfloat162 lp = __floats2bfloat162_rn(l0, l1);
                *(u32*)(smB_hi + i * PITCH_B + j * 2) = *(u32*)&hp;
                *(u32*)(smB_lo + i * PITCH_B + j * 2) = *(u32*)&lp;
            }
        }
        __syncthreads();
#pragma unroll
        for (int ks = 0; ks < 4; ks++) {
            u32 ahi[4], alo[4];
            LDSM4(ahi, adAhi + ks * 32);
            LDSM4(alo, adAlo + ks * 32);
#pragma unroll
            for (int p = 0; p < 8; p++) {
                u32 bhi[4], blo[4];
                LDSM4(bhi, adBhi + p * (16 * PITCH_B) + ks * 32);
                LDSM4(blo, adBlo + p * (16 * PITCH_B) + ks * 32);
                mma_bf16(acc[2 * p],     ahi, bhi);
                mma_bf16(acc[2 * p],     ahi, blo);
                mma_bf16(acc[2 * p],     alo, bhi);
                mma_bf16(acc[2 * p + 1], ahi, bhi + 2);
                mma_bf16(acc[2 * p + 1], ahi, blo + 2);
                mma_bf16(acc[2 * p + 1], alo, bhi + 2);
            }
        }
    }

    denS[tid] = den;
    __syncthreads();
    if (tid < 128) invD[tid] = 1.0f / (denS[2 * tid] + denS[2 * tid + 1]);
    __syncthreads();

    {
        const int dl = wp * 16 + (lane >> 2);
        const int il = 2 * (lane & 3);
#pragma unroll
        for (int nf = 0; nf < 16; nf++) {
            int ir = nf * 8 + il;
            float v0 = invD[ir], v1 = invD[ir + 1];
            float* p0 = out + (size_t)(base + i0 + ir) * 128 + dl;
            p0[0]        = acc[nf][0] * v0;
            p0[128]      = acc[nf][1] * v1;
            p0[8]        = acc[nf][2] * v0;
            p0[128 + 8]  = acc[nf][3] * v1;
        }
    }
}

// ---------------------------------------------------------------------------
extern "C" void kernel_launch(void* const* d_in, const int* in_sizes, int n_in,
                              void* d_out, int out_size) {
    const float* h   = (const float*)d_in[0];   // (4,32,512,128) f32
    const int*   adj = (const int*)d_in[1];     // (512,512) i32
    const float* W   = (const float*)d_in[2];   // (128,128) f32
    const float* a   = (const float*)d_in[3];   // (256,) f32
    float* out = (float*)d_out;                 // (4,32,512,128) f32

    const int attn_smem = 4 * 128 * PITCH_B;    // 73728 B
    cudaFuncSetAttribute(k_attn, cudaFuncAttributeMaxDynamicSharedMemorySize,
                         attn_smem);

    k_gemm<<<NROWS / 64, 256>>>(h, W, a);       // Wh^T(bf16 hi/lo) + exp tables
    k_adjbits<<<(NN * 16) / 256, 256>>>(adj);   // adj bitmask
    k_attn<<<BT * 4, 256, attn_smem>>>(out);    // mma.sync softmax-attention
}

// round 15
// speedup vs baseline: 1.0023x; 1.0023x over previous
#include <cuda_runtime.h>
#include <cuda_bf16.h>
#include <cstdint>

// Problem constants: B=4, T=32 -> BT=128 slices; N=512 nodes; F_in=D=128.
#define BT    128
#define NN    512
#define DD    128
#define NROWS (BT * NN)       // 65536 total node-rows

typedef unsigned long long u64;
typedef unsigned int       u32;
typedef unsigned short     u16;

// Scratch (allocation-free: __device__ globals)
__device__ float g_es[NROWS], g_ed[NROWS];
__device__ float g_F[NROWS], g_f[NROWS];           // exp(es), exp(0.2*es)
__device__ float g_G[NROWS], g_g[NROWS];           // exp(ed), exp(0.2*ed)
__device__ unsigned g_adjbits[NN * 16];            // bit j%32 of word [i][j/32]
// Wh transposed per slice, split into bf16 hi/lo: index [(bt*128 + d)*512 + j]
__device__ __align__(16) __nv_bfloat16 g_WhT_hi[NROWS * DD];
__device__ __align__(16) __nv_bfloat16 g_WhT_lo[NROWS * DD];

// ---- f32x2 helpers (k_gemm mainloop only) ----
__device__ __forceinline__ u64 pack2(float lo, float hi) {
    u64 r; asm("mov.b64 %0, {%1, %2};" : "=l"(r) : "f"(lo), "f"(hi)); return r;
}
__device__ __forceinline__ void ffma2(u64& d, u64 a, u64 b) {
    asm("fma.rn.f32x2 %0, %1, %2, %0;" : "+l"(d) : "l"(a), "l"(b));
}
__device__ __forceinline__ float2 unpack2(u64 v) {
    float2 f; asm("mov.b64 {%0, %1}, %2;" : "=f"(f.x), "=f"(f.y) : "l"(v)); return f;
}

__device__ __forceinline__ u32 smem_u32(const void* p) {
    u32 a;
    asm("{ .reg .u64 t; cvta.to.shared.u64 t, %1; cvt.u32.u64 %0, t; }"
        : "=r"(a) : "l"(p));
    return a;
}

// ---- family-portable tensor ops: ldmatrix + mma.sync (bf16, f32 acc) ----
#define LDSM4(r, addr) \
    asm volatile("ldmatrix.sync.aligned.m8n8.x4.shared.b16 {%0,%1,%2,%3}, [%4];" \
        : "=r"((r)[0]), "=r"((r)[1]), "=r"((r)[2]), "=r"((r)[3]) : "r"(addr))

__device__ __forceinline__ void mma_bf16(float* d, const u32* a, const u32* b) {
    asm volatile("mma.sync.aligned.m16n8k16.row.col.f32.bf16.bf16.f32 "
        "{%0,%1,%2,%3}, {%4,%5,%6,%7}, {%8,%9}, {%0,%1,%2,%3};"
        : "+f"(d[0]), "+f"(d[1]), "+f"(d[2]), "+f"(d[3])
        : "r"(a[0]), "r"(a[1]), "r"(a[2]), "r"(a[3]), "r"(b[0]), "r"(b[1]));
}

// ---------------------------------------------------------------------------
// Kernel 1: Wh = h @ W  (M=65536, K=128, N=128), tile 64x128.
// Epilogue: es/ed dot products + exp tables + smem-staged TRANSPOSED bf16
// hi/lo Wh store (coalesced STG.128 instead of scattered STG.16).
// ---------------------------------------------------------------------------
#define TBP 130                          // transpose buffer pitch (bf16), odd u32
__global__ __launch_bounds__(256) void k_gemm(const float* __restrict__ h,
                                              const float* __restrict__ W,
                                              const float* __restrict__ a) {
    __shared__ union {
        struct { float hs[64][33]; float Ws[32][128]; } mm;   // 24832 B
        __nv_bfloat16 tb[2][64 * TBP];                        // 33280 B
    } sm;
    __shared__ float sred[64][17];
    __shared__ float dred[64][17];

    const int row0 = blockIdx.x * 64;
    const int tid  = threadIdx.x;
    const int tx   = tid & 15;
    const int ty   = tid >> 4;

    u64 acc2[4][4];
#pragma unroll
    for (int r = 0; r < 4; r++)
#pragma unroll
        for (int d = 0; d < 4; d++) acc2[r][d] = 0ull;

    for (int k0 = 0; k0 < 128; k0 += 32) {
        __syncthreads();
#pragma unroll
        for (int l = 0; l < 2; l++) {
            int idx = tid + l * 256;
            int r = idx >> 3, c4 = (idx & 7) * 4;
            float4 v = *(const float4*)&h[(size_t)(row0 + r) * 128 + k0 + c4];
            sm.mm.hs[r][c4 + 0] = v.x; sm.mm.hs[r][c4 + 1] = v.y;
            sm.mm.hs[r][c4 + 2] = v.z; sm.mm.hs[r][c4 + 3] = v.w;
        }
#pragma unroll
        for (int l = 0; l < 4; l++) {
            int idx = tid + l * 256;
            int kk = idx >> 5, dc = (idx & 31) * 4;
            *(float4*)&sm.mm.Ws[kk][dc] = *(const float4*)&W[(k0 + kk) * 128 + dc];
        }
        __syncthreads();
#pragma unroll 8
        for (int k = 0; k < 32; k++) {
            ulonglong2 wa = *(const ulonglong2*)&sm.mm.Ws[k][tx * 8];
            ulonglong2 wb = *(const ulonglong2*)&sm.mm.Ws[k][tx * 8 + 4];
#pragma unroll
            for (int r = 0; r < 4; r++) {
                float hv = sm.mm.hs[ty + r * 16][k];
                u64 h2 = pack2(hv, hv);
                ffma2(acc2[r][0], h2, wa.x);
                ffma2(acc2[r][1], h2, wa.y);
                ffma2(acc2[r][2], h2, wb.x);
                ffma2(acc2[r][3], h2, wb.y);
            }
        }
    }
    __syncthreads();   // mainloop reads of hs/Ws done before tb overwrite

    float a_s[8], a_d[8];
#pragma unroll
    for (int d = 0; d < 8; d++) {
        a_s[d] = a[tx * 8 + d];
        a_d[d] = a[128 + tx * 8 + d];
    }

#pragma unroll
    for (int r = 0; r < 4; r++) {
        int rl = ty + r * 16;              // local j (0..63)
        float v[8];
        float2 p;
        p = unpack2(acc2[r][0]); v[0] = p.x; v[1] = p.y;
        p = unpack2(acc2[r][1]); v[2] = p.x; v[3] = p.y;
        p = unpack2(acc2[r][2]); v[4] = p.x; v[5] = p.y;
        p = unpack2(acc2[r][3]); v[6] = p.x; v[7] = p.y;
        float s = 0.f, dd = 0.f;
#pragma unroll
        for (int d = 0; d < 8; d += 2) {
            s  += v[d] * a_s[d]     + v[d + 1] * a_s[d + 1];
            dd += v[d] * a_d[d]     + v[d + 1] * a_d[d + 1];
            __nv_bfloat162 hp = __floats2bfloat162_rn(v[d], v[d + 1]);
            float l0 = v[d]     - __bfloat162float(hp.x);
            float l1 = v[d + 1] - __bfloat162float(hp.y);
            __nv_bfloat162 lp = __floats2bfloat162_rn(l0, l1);
            *(u32*)&sm.tb[0][rl * TBP + tx * 8 + d] = *(u32*)&hp;
            *(u32*)&sm.tb[1][rl * TBP + tx * 8 + d] = *(u32*)&lp;
        }
        sred[rl][tx] = s;
        dred[rl][tx] = dd;
    }
    __syncthreads();

    // es/ed reduction + exp tables
    if (tid < 64) {
        float s = 0.f, dd = 0.f;
#pragma unroll
        for (int t = 0; t < 16; t++) { s += sred[tid][t]; dd += dred[tid][t]; }
        int n = row0 + tid;
        g_es[n] = s;  g_ed[n] = dd;
        g_F[n] = expf(s);         g_f[n] = expf(0.2f * s);
        g_G[n] = expf(dd);        g_g[n] = expf(0.2f * dd);
    }

    // transposed coalesced store: thread = d-row (tid>>1), j-half (tid&1)
    {
        const int bts   = row0 >> 9;
        const int jcol0 = row0 & 511;
        const int dr    = tid >> 1;
        const int jb    = (tid & 1) * 32;
        size_t gbase = ((size_t)bts * 128 + dr) * 512 + jcol0 + jb;
#pragma unroll
        for (int buf = 0; buf < 2; buf++) {
            __nv_bfloat16* gdst = buf ? g_WhT_lo : g_WhT_hi;
            const __nv_bfloat16* src = sm.tb[buf];
#pragma unroll
            for (int q = 0; q < 4; q++) {
                u16 w[8];
#pragma unroll
                for (int e = 0; e < 8; e++)
                    w[e] = *(const u16*)&src[(jb + q * 8 + e) * TBP + dr];
                *(uint4*)&gdst[gbase + q * 8] = *(uint4*)w;
            }
        }
    }
}

// ---------------------------------------------------------------------------
// Kernel 2: adjacency -> bitmask
// ---------------------------------------------------------------------------
__global__ __launch_bounds__(256) void k_adjbits(const int* __restrict__ adj) {
    int idx = blockIdx.x * 256 + threadIdx.x;
    int i = idx >> 4, w = idx & 15;
    unsigned bits = 0;
#pragma unroll
    for (int b = 0; b < 32; b++)
        if (adj[i * NN + w * 32 + b] > 0) bits |= (1u << b);
    g_adjbits[idx] = bits;
}

// ---------------------------------------------------------------------------
// Kernel 3: tensor-core (mma.sync bf16) fused masked-softmax-attention.
// D[d][i] = sum_j WhT[d][j] * C[i][j];  out[i][d] = D[d][i] / den[i]
// (unchanged from R10 passing version)
// ---------------------------------------------------------------------------
#define PITCH_B 144                      // 72 bf16 per row
__global__ __launch_bounds__(256) void k_attn(float* __restrict__ out) {
    extern __shared__ char dyn[];
    char* smA_hi = dyn;                  // [128][72] bf16 = 18432 B
    char* smA_lo = dyn + 18432;
    char* smB_hi = dyn + 36864;
    char* smB_lo = dyn + 55296;          // total 73728 B

    __shared__ unsigned bitsS[128 * 16];
    __shared__ float edS[64], GS[64], gS[64];
    __shared__ float denS[256];
    __shared__ float invD[128];

    const int tid  = threadIdx.x;
    const int lane = tid & 31;
    const int wp   = tid >> 5;
    const int bt   = blockIdx.x >> 2;
    const int tile = blockIdx.x & 3;
    const int base = bt * NN;
    const int i0   = tile * 128;

#pragma unroll
    for (int l = 0; l < 2; l++) {
        int idx4 = tid + l * 256;
        int r = idx4 >> 2, w4 = (idx4 & 3) * 4;
        *(uint4*)&bitsS[r * 16 + w4] = *(const uint4*)&g_adjbits[(i0 + r) * 16 + w4];
    }

    const int i    = tid >> 1;
    const int half = tid & 1;
    const float esv = g_es[base + i0 + i];
    const float Fv  = g_F[base + i0 + i];
    const float fv  = g_f[base + i0 + i];
    float den = 0.f;

    const __nv_bfloat16* srcHi = g_WhT_hi + (size_t)bt * 128 * 512;
    const __nv_bfloat16* srcLo = g_WhT_lo + (size_t)bt * 128 * 512;

    const int arow  = (lane & 7) + ((lane >> 3) & 1) * 8;
    const int akoff = (lane >> 4) * 8;
    const int brow  = (lane & 7) + (lane >> 4) * 8;
    const int bkoff = ((lane >> 3) & 1) * 8;
    const u32 adAhi = smem_u32(smA_hi) + (wp * 16 + arow) * PITCH_B + akoff * 2;
    const u32 adAlo = smem_u32(smA_lo) + (wp * 16 + arow) * PITCH_B + akoff * 2;
    const u32 adBhi = smem_u32(smB_hi) + brow * PITCH_B + bkoff * 2;
    const u32 adBlo = smem_u32(smB_lo) + brow * PITCH_B + bkoff * 2;

    float acc[16][4];
#pragma unroll
    for (int nf = 0; nf < 16; nf++)
#pragma unroll
        for (int q = 0; q < 4; q++) acc[nf][q] = 0.f;

    for (int ch = 0; ch < 8; ch++) {
        const int j0 = ch * 64;
        __syncthreads();
        if (tid < 64)       edS[tid]      = g_ed[base + j0 + tid];
        else if (tid < 128) GS[tid - 64]  = g_G[base + j0 + tid - 64];
        else if (tid < 192) gS[tid - 128] = g_g[base + j0 + tid - 128];
        {
            const int slot = tid & 7;
            const int drow = tid >> 3;
#pragma unroll
            for (int it = 0; it < 4; it++) {
                int d = drow + it * 32;
                size_t off = (size_t)d * 512 + j0 + slot * 8;
                *(uint4*)(smA_hi + d * PITCH_B + slot * 16) = *(const uint4*)(srcHi + off);
                *(uint4*)(smA_lo + d * PITCH_B + slot * 16) = *(const uint4*)(srcLo + off);
            }
        }
        __syncthreads();
        {
            unsigned bits = bitsS[i * 16 + ch * 2 + half];
#pragma unroll
            for (int jj = 0; jj < 32; jj += 2) {
                int j = half * 32 + jj;
                float c0 = 0.f, c1 = 0.f;
                if ((bits >> jj) & 1u) {
                    float t = esv + edS[j];
                    c0 = (t > 0.f) ? Fv * GS[j] : fv * gS[j];
                }
                if ((bits >> (jj + 1)) & 1u) {
                    float t = esv + edS[j + 1];
                    c1 = (t > 0.f) ? Fv * GS[j + 1] : fv * gS[j + 1];
                }
                den += c0 + c1;
                __nv_bfloat162 hp = __floats2bfloat162_rn(c0, c1);
                float l0 = c0 - __bfloat162float(hp.x);
                float l1 = c1 - __bfloat162float(hp.y);
                __nv_bfloat162 lp = __floats2bfloat162_rn(l0, l1);
                *(u32*)(smB_hi + i * PITCH_B + j * 2) = *(u32*)&hp;
                *(u32*)(smB_lo + i * PITCH_B + j * 2) = *(u32*)&lp;
            }
        }
        __syncthreads();
#pragma unroll
        for (int ks = 0; ks < 4; ks++) {
            u32 ahi[4], alo[4];
            LDSM4(ahi, adAhi + ks * 32);
            LDSM4(alo, adAlo + ks * 32);
#pragma unroll
            for (int p = 0; p < 8; p++) {
                u32 bhi[4], blo[4];
                LDSM4(bhi, adBhi + p * (16 * PITCH_B) + ks * 32);
                LDSM4(blo, adBlo + p * (16 * PITCH_B) + ks * 32);
                mma_bf16(acc[2 * p],     ahi, bhi);
                mma_bf16(acc[2 * p],     ahi, blo);
                mma_bf16(acc[2 * p],     alo, bhi);
                mma_bf16(acc[2 * p + 1], ahi, bhi + 2);
                mma_bf16(acc[2 * p + 1], ahi, blo + 2);
                mma_bf16(acc[2 * p + 1], alo, bhi + 2);
            }
        }
    }

    denS[tid] = den;
    __syncthreads();
    if (tid < 128) invD[tid] = 1.0f / (denS[2 * tid] + denS[2 * tid + 1]);
    __syncthreads();

    {
        const int dl = wp * 16 + (lane >> 2);
        const int il = 2 * (lane & 3);
#pragma unroll
        for (int nf = 0; nf < 16; nf++) {
            int ir = nf * 8 + il;
            float v0 = invD[ir], v1 = invD[ir + 1];
            float* p0 = out + (size_t)(base + i0 + ir) * 128 + dl;
            p0[0]        = acc[nf][0] * v0;
            p0[128]      = acc[nf][1] * v1;
            p0[8]        = acc[nf][2] * v0;
            p0[128 + 8]  = acc[nf][3] * v1;
        }
    }
}

// ---------------------------------------------------------------------------
extern "C" void kernel_launch(void* const* d_in, const int* in_sizes, int n_in,
                              void* d_out, int out_size) {
    const float* h   = (const float*)d_in[0];   // (4,32,512,128) f32
    const int*   adj = (const int*)d_in[1];     // (512,512) i32
    const float* W   = (const float*)d_in[2];   // (128,128) f32
    const float* a   = (const float*)d_in[3];   // (256,) f32
    float* out = (float*)d_out;                 // (4,32,512,128) f32

    const int attn_smem = 4 * 128 * PITCH_B;    // 73728 B
    cudaFuncSetAttribute(k_attn, cudaFuncAttributeMaxDynamicSharedMemorySize,
                         attn_smem);

    k_gemm<<<NROWS / 64, 256>>>(h, W, a);       // Wh^T(bf16 hi/lo) + exp tables
    k_adjbits<<<(NN * 16) / 256, 256>>>(adj);   // adj bitmask
    k_attn<<<BT * 4, 256, attn_smem>>>(out);    // mma.sync softmax-attention
}

// round 16
// speedup vs baseline: 1.1188x; 1.1163x over previous
#include <cuda_runtime.h>
#include <cuda_bf16.h>
#include <cstdint>

// Problem constants: B=4, T=32 -> BT=128 slices; N=512 nodes; F_in=D=128.
#define BT    128
#define NN    512
#define DD    128
#define NROWS (BT * NN)       // 65536 total node-rows

typedef unsigned long long u64;
typedef unsigned int       u32;
typedef unsigned short     u16;

// Scratch (allocation-free: __device__ globals)
__device__ float g_es[NROWS], g_ed[NROWS];
__device__ float g_F[NROWS], g_f[NROWS];           // exp(es), exp(0.2*es)
__device__ float g_G[NROWS], g_g[NROWS];           // exp(ed), exp(0.2*ed)
__device__ unsigned g_adjbits[NN * 16];            // bit j%32 of word [i][j/32]
// Wh transposed per slice, split into bf16 hi/lo: index [(bt*128 + d)*512 + j]
__device__ __align__(16) __nv_bfloat16 g_WhT_hi[NROWS * DD];
__device__ __align__(16) __nv_bfloat16 g_WhT_lo[NROWS * DD];
// W transposed + split: [d][k] bf16
__device__ __align__(16) __nv_bfloat16 g_WT_hi[DD * DD];
__device__ __align__(16) __nv_bfloat16 g_WT_lo[DD * DD];

__device__ __forceinline__ u32 smem_u32(const void* p) {
    u32 a;
    asm("{ .reg .u64 t; cvta.to.shared.u64 t, %1; cvt.u32.u64 %0, t; }"
        : "=r"(a) : "l"(p));
    return a;
}

// ---- family-portable tensor ops: ldmatrix + mma.sync (bf16, f32 acc) ----
#define LDSM4(r, addr) \
    asm volatile("ldmatrix.sync.aligned.m8n8.x4.shared.b16 {%0,%1,%2,%3}, [%4];" \
        : "=r"((r)[0]), "=r"((r)[1]), "=r"((r)[2]), "=r"((r)[3]) : "r"(addr))

__device__ __forceinline__ void mma_bf16(float* d, const u32* a, const u32* b) {
    asm volatile("mma.sync.aligned.m16n8k16.row.col.f32.bf16.bf16.f32 "
        "{%0,%1,%2,%3}, {%4,%5,%6,%7}, {%8,%9}, {%0,%1,%2,%3};"
        : "+f"(d[0]), "+f"(d[1]), "+f"(d[2]), "+f"(d[3])
        : "r"(a[0]), "r"(a[1]), "r"(a[2]), "r"(a[3]), "r"(b[0]), "r"(b[1]));
}

// ---------------------------------------------------------------------------
// Kernel 0: W -> W^T bf16 hi/lo (one block; W stays L2-resident)
// ---------------------------------------------------------------------------
__global__ __launch_bounds__(256) void k_prepW(const float* __restrict__ W) {
    const int d  = threadIdx.x & 127;
    const int kh = (threadIdx.x >> 7) * 64;
    for (int k0 = kh; k0 < kh + 64; k0 += 8) {
        u16 wh[8], wl[8];
#pragma unroll
        for (int e = 0; e < 8; e++) {
            float v = W[(k0 + e) * 128 + d];
            __nv_bfloat16 hb = __float2bfloat16(v);
            __nv_bfloat16 lb = __float2bfloat16(v - __bfloat162float(hb));
            wh[e] = *(u16*)&hb;
            wl[e] = *(u16*)&lb;
        }
        *(uint4*)&g_WT_hi[d * 128 + k0] = *(uint4*)wh;
        *(uint4*)&g_WT_lo[d * 128 + k0] = *(uint4*)wl;
    }
}

// ---------------------------------------------------------------------------
// Kernel 1: Wh = h @ W via mma.sync bf16 hi/lo (3-term split).
// Block = 128 rows x 128 cols, K=128 in 8 k16-steps. 8 warps: warp wp owns
// m16 strip (rows wp*16..+15) x n128. Epilogue: es/ed from fragments +
// smem-staged transposed bf16 hi/lo WhT store (coalesced STG.128).
// Dynamic smem: mainloop WT(2x34816) + hs(2x6144) = 81920 B; epilogue tb
// (2x33280 B) aliases the same region.
// ---------------------------------------------------------------------------
#define WTP 272                          // WT row pitch bytes (136 bf16)
#define HSP 48                           // hs row pitch bytes (24 bf16)
#define TBPB 260                         // tb row pitch bytes (130 bf16)
__global__ __launch_bounds__(256) void k_gemm(const float* __restrict__ h,
                                              const float* __restrict__ a) {
    extern __shared__ char dyn[];
    char* WT_hi = dyn;                   // [128][136] bf16
    char* WT_lo = dyn + 34816;
    char* hs_hi = dyn + 69632;           // [128][24] bf16
    char* hs_lo = dyn + 75776;
    char* tb0   = dyn;                   // epilogue alias: [128][130] bf16
    char* tb1   = dyn + 33280;

    __shared__ float sredS[128], dredS[128];
    __shared__ float aT[256];

    const int row0 = blockIdx.x * 128;
    const int tid  = threadIdx.x;
    const int lane = tid & 31;
    const int wp   = tid >> 5;

    aT[tid] = a[tid];

    // stage WT hi/lo: 2048 uint4 per buf, 8 per thread
#pragma unroll
    for (int l = 0; l < 8; l++) {
        int idx = tid + l * 256;
        int d = idx >> 4, q = idx & 15;
        *(uint4*)(WT_hi + d * WTP + q * 16) = *(const uint4*)&g_WT_hi[d * 128 + q * 8];
        *(uint4*)(WT_lo + d * WTP + q * 16) = *(const uint4*)&g_WT_lo[d * 128 + q * 8];
    }

    // ldmatrix lane->address maps (same as k_attn)
    const int arow  = (lane & 7) + ((lane >> 3) & 1) * 8;
    const int akoff = (lane >> 4) * 8;
    const int brow  = (lane & 7) + (lane >> 4) * 8;
    const int bkoff = ((lane >> 3) & 1) * 8;
    const u32 adAhi = smem_u32(hs_hi) + (wp * 16 + arow) * HSP + akoff * 2;
    const u32 adAlo = smem_u32(hs_lo) + (wp * 16 + arow) * HSP + akoff * 2;
    const u32 adBhi = smem_u32(WT_hi) + brow * WTP + bkoff * 2;
    const u32 adBlo = smem_u32(WT_lo) + brow * WTP + bkoff * 2;

    float acc[16][4];
#pragma unroll
    for (int nf = 0; nf < 16; nf++)
#pragma unroll
        for (int q = 0; q < 4; q++) acc[nf][q] = 0.f;

    const int hr  = tid >> 1;            // h row this thread stages
    const int hk  = (tid & 1) * 8;       // k-offset (8 floats)

    for (int ks = 0; ks < 8; ks++) {
        __syncthreads();                 // prior LDSM of hs done / WT staged
        // load + split h chunk [128][16]
        {
            const float* hp = &h[(size_t)(row0 + hr) * 128 + ks * 16 + hk];
            float4 v0 = *(const float4*)hp;
            float4 v1 = *(const float4*)(hp + 4);
            float v[8] = {v0.x, v0.y, v0.z, v0.w, v1.x, v1.y, v1.z, v1.w};
            u32 hh[4], ll[4];
#pragma unroll
            for (int e = 0; e < 4; e++) {
                __nv_bfloat162 hp2 = __floats2bfloat162_rn(v[2*e], v[2*e+1]);
                float l0 = v[2*e]   - __bfloat162float(hp2.x);
                float l1 = v[2*e+1] - __bfloat162float(hp2.y);
                __nv_bfloat162 lp2 = __floats2bfloat162_rn(l0, l1);
                hh[e] = *(u32*)&hp2;
                ll[e] = *(u32*)&lp2;
            }
            *(uint4*)(hs_hi + hr * HSP + hk * 2) = *(uint4*)hh;
            *(uint4*)(hs_lo + hr * HSP + hk * 2) = *(uint4*)ll;
        }
        __syncthreads();
        // MMA: A = h strip (m16k16), B = WT (n128), 3 split terms
        u32 ahi[4], alo[4];
        LDSM4(ahi, adAhi);
        LDSM4(alo, adAlo);
#pragma unroll
        for (int p = 0; p < 8; p++) {
            u32 bhi[4], blo[4];
            LDSM4(bhi, adBhi + p * (16 * WTP) + ks * 32);
            LDSM4(blo, adBlo + p * (16 * WTP) + ks * 32);
            mma_bf16(acc[2 * p],     ahi, bhi);
            mma_bf16(acc[2 * p],     ahi, blo);
            mma_bf16(acc[2 * p],     alo, bhi);
            mma_bf16(acc[2 * p + 1], ahi, bhi + 2);
            mma_bf16(acc[2 * p + 1], ahi, blo + 2);
            mma_bf16(acc[2 * p + 1], alo, bhi + 2);
        }
    }
    __syncthreads();                     // mainloop smem reads done (tb alias)

    // es/ed from fragments: lane holds rows ia=wp*16+(lane>>2), ib=ia+8,
    // cols c = nf*8 + 2*(lane&3), c+1
    const int cb = 2 * (lane & 3);
    const int ia = wp * 16 + (lane >> 2);
    {
        float sa = 0.f, sb = 0.f, da = 0.f, db = 0.f;
#pragma unroll
        for (int nf = 0; nf < 16; nf++) {
            int c = nf * 8 + cb;
            float a0 = aT[c], a1 = aT[c + 1];
            float b0 = aT[128 + c], b1 = aT[128 + c + 1];
            sa += acc[nf][0] * a0 + acc[nf][1] * a1;
            da += acc[nf][0] * b0 + acc[nf][1] * b1;
            sb += acc[nf][2] * a0 + acc[nf][3] * a1;
            db += acc[nf][2] * b0 + acc[nf][3] * b1;
        }
#pragma unroll
        for (int off = 1; off <= 2; off <<= 1) {
            sa += __shfl_xor_sync(0xffffffffu, sa, off);
            sb += __shfl_xor_sync(0xffffffffu, sb, off);
            da += __shfl_xor_sync(0xffffffffu, da, off);
            db += __shfl_xor_sync(0xffffffffu, db, off);
        }
        if ((lane & 3) == 0) {
            sredS[ia] = sa;     dredS[ia] = da;
            sredS[ia + 8] = sb; dredS[ia + 8] = db;
        }
    }

    // fragments -> tb (bf16 hi/lo), [i][d] layout
#pragma unroll
    for (int nf = 0; nf < 16; nf++) {
        int c = nf * 8 + cb;
        __nv_bfloat162 hA = __floats2bfloat162_rn(acc[nf][0], acc[nf][1]);
        __nv_bfloat162 lA = __floats2bfloat162_rn(
            acc[nf][0] - __bfloat162float(hA.x),
            acc[nf][1] - __bfloat162float(hA.y));
        __nv_bfloat162 hB = __floats2bfloat162_rn(acc[nf][2], acc[nf][3]);
        __nv_bfloat162 lB = __floats2bfloat162_rn(
            acc[nf][2] - __bfloat162float(hB.x),
            acc[nf][3] - __bfloat162float(hB.y));
        *(u32*)(tb0 + ia * TBPB + c * 2)       = *(u32*)&hA;
        *(u32*)(tb1 + ia * TBPB + c * 2)       = *(u32*)&lA;
        *(u32*)(tb0 + (ia + 8) * TBPB + c * 2) = *(u32*)&hB;
        *(u32*)(tb1 + (ia + 8) * TBPB + c * 2) = *(u32*)&lB;
    }
    __syncthreads();

    // exp tables
    if (tid < 128) {
        int n = row0 + tid;
        float s = sredS[tid], dd = dredS[tid];
        g_es[n] = s;  g_ed[n] = dd;
        g_F[n] = expf(s);         g_f[n] = expf(0.2f * s);
        g_G[n] = expf(dd);        g_g[n] = expf(0.2f * dd);
    }

    // transposed coalesced store: thread = d-row (tid>>1), j-half (tid&1)
    {
        const int bts = row0 >> 9;
        const int jc0 = row0 & 511;
        const int dr  = tid >> 1;
        const int jb  = (tid & 1) * 64;
        size_t gbase = ((size_t)bts * 128 + dr) * 512 + jc0 + jb;
#pragma unroll
        for (int buf = 0; buf < 2; buf++) {
            __nv_bfloat16* gdst = buf ? g_WhT_lo : g_WhT_hi;
            const char* src = buf ? tb1 : tb0;
#pragma unroll
            for (int q = 0; q < 8; q++) {
                u16 w[8];
#pragma unroll
                for (int e = 0; e < 8; e++)
                    w[e] = *(const u16*)(src + (jb + q * 8 + e) * TBPB + dr * 2);
                *(uint4*)&gdst[gbase + q * 8] = *(uint4*)w;
            }
        }
    }
}

// ---------------------------------------------------------------------------
// Kernel 2: adjacency -> bitmask
// ---------------------------------------------------------------------------
__global__ __launch_bounds__(256) void k_adjbits(const int* __restrict__ adj) {
    int idx = blockIdx.x * 256 + threadIdx.x;
    int i = idx >> 4, w = idx & 15;
    unsigned bits = 0;
#pragma unroll
    for (int b = 0; b < 32; b++)
        if (adj[i * NN + w * 32 + b] > 0) bits |= (1u << b);
    g_adjbits[idx] = bits;
}

// ---------------------------------------------------------------------------
// Kernel 3: tensor-core (mma.sync bf16) fused masked-softmax-attention.
// (unchanged from R15 passing version)
// ---------------------------------------------------------------------------
#define PITCH_B 144                      // 72 bf16 per row
__global__ __launch_bounds__(256) void k_attn(float* __restrict__ out) {
    extern __shared__ char dyn[];
    char* smA_hi = dyn;                  // [128][72] bf16 = 18432 B
    char* smA_lo = dyn + 18432;
    char* smB_hi = dyn + 36864;
    char* smB_lo = dyn + 55296;          // total 73728 B

    __shared__ unsigned bitsS[128 * 16];
    __shared__ float edS[64], GS[64], gS[64];
    __shared__ float denS[256];
    __shared__ float invD[128];

    const int tid  = threadIdx.x;
    const int lane = tid & 31;
    const int wp   = tid >> 5;
    const int bt   = blockIdx.x >> 2;
    const int tile = blockIdx.x & 3;
    const int base = bt * NN;
    const int i0   = tile * 128;

#pragma unroll
    for (int l = 0; l < 2; l++) {
        int idx4 = tid + l * 256;
        int r = idx4 >> 2, w4 = (idx4 & 3) * 4;
        *(uint4*)&bitsS[r * 16 + w4] = *(const uint4*)&g_adjbits[(i0 + r) * 16 + w4];
    }

    const int i    = tid >> 1;
    const int half = tid & 1;
    const float esv = g_es[base + i0 + i];
    const float Fv  = g_F[base + i0 + i];
    const float fv  = g_f[base + i0 + i];
    float den = 0.f;

    const __nv_bfloat16* srcHi = g_WhT_hi + (size_t)bt * 128 * 512;
    const __nv_bfloat16* srcLo = g_WhT_lo + (size_t)bt * 128 * 512;

    const int arow  = (lane & 7) + ((lane >> 3) & 1) * 8;
    const int akoff = (lane >> 4) * 8;
    const int brow  = (lane & 7) + (lane >> 4) * 8;
    const int bkoff = ((lane >> 3) & 1) * 8;
    const u32 adAhi = smem_u32(smA_hi) + (wp * 16 + arow) * PITCH_B + akoff * 2;
    const u32 adAlo = smem_u32(smA_lo) + (wp * 16 + arow) * PITCH_B + akoff * 2;
    const u32 adBhi = smem_u32(smB_hi) + brow * PITCH_B + bkoff * 2;
    const u32 adBlo = smem_u32(smB_lo) + brow * PITCH_B + bkoff * 2;

    float acc[16][4];
#pragma unroll
    for (int nf = 0; nf < 16; nf++)
#pragma unroll
        for (int q = 0; q < 4; q++) acc[nf][q] = 0.f;

    for (int ch = 0; ch < 8; ch++) {
        const int j0 = ch * 64;
        __syncthreads();
        if (tid < 64)       edS[tid]      = g_ed[base + j0 + tid];
        else if (tid < 128) GS[tid - 64]  = g_G[base + j0 + tid - 64];
        else if (tid < 192) gS[tid - 128] = g_g[base + j0 + tid - 128];
        {
            const int slot = tid & 7;
            const int drow = tid >> 3;
#pragma unroll
            for (int it = 0; it < 4; it++) {
                int d = drow + it * 32;
                size_t off = (size_t)d * 512 + j0 + slot * 8;
                *(uint4*)(smA_hi + d * PITCH_B + slot * 16) = *(const uint4*)(srcHi + off);
                *(uint4*)(smA_lo + d * PITCH_B + slot * 16) = *(const uint4*)(srcLo + off);
            }
        }
        __syncthreads();
        {
            unsigned bits = bitsS[i * 16 + ch * 2 + half];
#pragma unroll
            for (int jj = 0; jj < 32; jj += 2) {
                int j = half * 32 + jj;
                float c0 = 0.f, c1 = 0.f;
                if ((bits >> jj) & 1u) {
                    float t = esv + edS[j];
                    c0 = (t > 0.f) ? Fv * GS[j] : fv * gS[j];
                }
                if ((bits >> (jj + 1)) & 1u) {
                    float t = esv + edS[j + 1];
                    c1 = (t > 0.f) ? Fv * GS[j + 1] : fv * gS[j + 1];
                }
                den += c0 + c1;
                __nv_bfloat162 hp = __floats2bfloat162_rn(c0, c1);
                float l0 = c0 - __bfloat162float(hp.x);
                float l1 = c1 - __bfloat162float(hp.y);
                __nv_bfloat162 lp = __floats2bfloat162_rn(l0, l1);
                *(u32*)(smB_hi + i * PITCH_B + j * 2) = *(u32*)&hp;
                *(u32*)(smB_lo + i * PITCH_B + j * 2) = *(u32*)&lp;
            }
        }
        __syncthreads();
#pragma unroll
        for (int ks = 0; ks < 4; ks++) {
            u32 ahi[4], alo[4];
            LDSM4(ahi, adAhi + ks * 32);
            LDSM4(alo, adAlo + ks * 32);
#pragma unroll
            for (int p = 0; p < 8; p++) {
                u32 bhi[4], blo[4];
                LDSM4(bhi, adBhi + p * (16 * PITCH_B) + ks * 32);
                LDSM4(blo, adBlo + p * (16 * PITCH_B) + ks * 32);
                mma_bf16(acc[2 * p],     ahi, bhi);
                mma_bf16(acc[2 * p],     ahi, blo);
                mma_bf16(acc[2 * p],     alo, bhi);
                mma_bf16(acc[2 * p + 1], ahi, bhi + 2);
                mma_bf16(acc[2 * p + 1], ahi, blo + 2);
                mma_bf16(acc[2 * p + 1], alo, bhi + 2);
            }
        }
    }

    denS[tid] = den;
    __syncthreads();
    if (tid < 128) invD[tid] = 1.0f / (denS[2 * tid] + denS[2 * tid + 1]);
    __syncthreads();

    {
        const int dl = wp * 16 + (lane >> 2);
        const int il = 2 * (lane & 3);
#pragma unroll
        for (int nf = 0; nf < 16; nf++) {
            int ir = nf * 8 + il;
            float v0 = invD[ir], v1 = invD[ir + 1];
            float* p0 = out + (size_t)(base + i0 + ir) * 128 + dl;
            p0[0]        = acc[nf][0] * v0;
            p0[128]      = acc[nf][1] * v1;
            p0[8]        = acc[nf][2] * v0;
            p0[128 + 8]  = acc[nf][3] * v1;
        }
    }
}

// ---------------------------------------------------------------------------
extern "C" void kernel_launch(void* const* d_in, const int* in_sizes, int n_in,
                              void* d_out, int out_size) {
    const float* h   = (const float*)d_in[0];   // (4,32,512,128) f32
    const int*   adj = (const int*)d_in[1];     // (512,512) i32
    const float* W   = (const float*)d_in[2];   // (128,128) f32
    const float* a   = (const float*)d_in[3];   // (256,) f32
    float* out = (float*)d_out;                 // (4,32,512,128) f32

    const int gemm_smem = 81920;                // WT + hs (tb aliases)
    const int attn_smem = 4 * 128 * PITCH_B;    // 73728 B
    cudaFuncSetAttribute(k_gemm, cudaFuncAttributeMaxDynamicSharedMemorySize,
                         gemm_smem);
    cudaFuncSetAttribute(k_attn, cudaFuncAttributeMaxDynamicSharedMemorySize,
                         attn_smem);

    k_prepW<<<1, 256>>>(W);                         // W^T bf16 hi/lo
    k_gemm<<<NROWS / 128, 256, gemm_smem>>>(h, a);  // Wh^T + exp tables (mma)
    k_adjbits<<<(NN * 16) / 256, 256>>>(adj);       // adj bitmask
    k_attn<<<BT * 4, 256, attn_smem>>>(out);        // mma.sync softmax-attn
}

// round 17
// speedup vs baseline: 1.3653x; 1.2203x over previous
#include <cuda_runtime.h>
#include <cuda_bf16.h>
#include <cstdint>

// Problem constants: B=4, T=32 -> BT=128 slices; N=512 nodes; F_in=D=128.
#define BT    128
#define NN    512
#define DD    128
#define NROWS (BT * NN)       // 65536 total node-rows

typedef unsigned long long u64;
typedef unsigned int       u32;
typedef unsigned short     u16;

// Scratch (allocation-free: __device__ globals)
__device__ float g_es[NROWS], g_ed[NROWS];
__device__ float g_F[NROWS], g_f[NROWS];           // exp(es), exp(0.2*es)
__device__ float g_G[NROWS], g_g[NROWS];           // exp(ed), exp(0.2*ed)
__device__ unsigned g_adjbits[NN * 16];            // bit j%32 of word [i][j/32]
// Wh transposed per slice, split into bf16 hi/lo: index [(bt*128 + d)*512 + j]
__device__ __align__(16) __nv_bfloat16 g_WhT_hi[NROWS * DD];
__device__ __align__(16) __nv_bfloat16 g_WhT_lo[NROWS * DD];
// W transposed + split: [d][k] bf16
__device__ __align__(16) __nv_bfloat16 g_WT_hi[DD * DD];
__device__ __align__(16) __nv_bfloat16 g_WT_lo[DD * DD];

__device__ __forceinline__ u32 smem_u32(const void* p) {
    u32 a;
    asm("{ .reg .u64 t; cvta.to.shared.u64 t, %1; cvt.u32.u64 %0, t; }"
        : "=r"(a) : "l"(p));
    return a;
}

// ---- family-portable tensor ops: ldmatrix + mma.sync (bf16, f32 acc) ----
#define LDSM4(r, addr) \
    asm volatile("ldmatrix.sync.aligned.m8n8.x4.shared.b16 {%0,%1,%2,%3}, [%4];" \
        : "=r"((r)[0]), "=r"((r)[1]), "=r"((r)[2]), "=r"((r)[3]) : "r"(addr))

__device__ __forceinline__ void mma_bf16(float* d, const u32* a, const u32* b) {
    asm volatile("mma.sync.aligned.m16n8k16.row.col.f32.bf16.bf16.f32 "
        "{%0,%1,%2,%3}, {%4,%5,%6,%7}, {%8,%9}, {%0,%1,%2,%3};"
        : "+f"(d[0]), "+f"(d[1]), "+f"(d[2]), "+f"(d[3])
        : "r"(a[0]), "r"(a[1]), "r"(a[2]), "r"(a[3]), "r"(b[0]), "r"(b[1]));
}

// ---------------------------------------------------------------------------
// Kernel 0: W -> W^T bf16 hi/lo (one block; W stays L2-resident)
// ---------------------------------------------------------------------------
__global__ __launch_bounds__(256) void k_prepW(const float* __restrict__ W) {
    const int d  = threadIdx.x & 127;
    const int kh = (threadIdx.x >> 7) * 64;
    for (int k0 = kh; k0 < kh + 64; k0 += 8) {
        u16 wh[8], wl[8];
#pragma unroll
        for (int e = 0; e < 8; e++) {
            float v = W[(k0 + e) * 128 + d];
            __nv_bfloat16 hb = __float2bfloat16(v);
            __nv_bfloat16 lb = __float2bfloat16(v - __bfloat162float(hb));
            wh[e] = *(u16*)&hb;
            wl[e] = *(u16*)&wl[e], wl[e] = *(u16*)&lb;
        }
        *(uint4*)&g_WT_hi[d * 128 + k0] = *(uint4*)wh;
        *(uint4*)&g_WT_lo[d * 128 + k0] = *(uint4*)wl;
    }
}

// ---------------------------------------------------------------------------
// Kernel 1: Wh = h @ W via mma.sync bf16 hi/lo (3-term split).
// (unchanged from R16 passing version)
// ---------------------------------------------------------------------------
#define WTP 272                          // WT row pitch bytes (136 bf16)
#define HSP 48                           // hs row pitch bytes (24 bf16)
#define TBPB 260                         // tb row pitch bytes (130 bf16)
__global__ __launch_bounds__(256) void k_gemm(const float* __restrict__ h,
                                              const float* __restrict__ a) {
    extern __shared__ char dyn[];
    char* WT_hi = dyn;                   // [128][136] bf16
    char* WT_lo = dyn + 34816;
    char* hs_hi = dyn + 69632;           // [128][24] bf16
    char* hs_lo = dyn + 75776;
    char* tb0   = dyn;                   // epilogue alias: [128][130] bf16
    char* tb1   = dyn + 33280;

    __shared__ float sredS[128], dredS[128];
    __shared__ float aT[256];

    const int row0 = blockIdx.x * 128;
    const int tid  = threadIdx.x;
    const int lane = tid & 31;
    const int wp   = tid >> 5;

    aT[tid] = a[tid];

#pragma unroll
    for (int l = 0; l < 8; l++) {
        int idx = tid + l * 256;
        int d = idx >> 4, q = idx & 15;
        *(uint4*)(WT_hi + d * WTP + q * 16) = *(const uint4*)&g_WT_hi[d * 128 + q * 8];
        *(uint4*)(WT_lo + d * WTP + q * 16) = *(const uint4*)&g_WT_lo[d * 128 + q * 8];
    }

    const int arow  = (lane & 7) + ((lane >> 3) & 1) * 8;
    const int akoff = (lane >> 4) * 8;
    const int brow  = (lane & 7) + (lane >> 4) * 8;
    const int bkoff = ((lane >> 3) & 1) * 8;
    const u32 adAhi = smem_u32(hs_hi) + (wp * 16 + arow) * HSP + akoff * 2;
    const u32 adAlo = smem_u32(hs_lo) + (wp * 16 + arow) * HSP + akoff * 2;
    const u32 adBhi = smem_u32(WT_hi) + brow * WTP + bkoff * 2;
    const u32 adBlo = smem_u32(WT_lo) + brow * WTP + bkoff * 2;

    float acc[16][4];
#pragma unroll
    for (int nf = 0; nf < 16; nf++)
#pragma unroll
        for (int q = 0; q < 4; q++) acc[nf][q] = 0.f;

    const int hr  = tid >> 1;
    const int hk  = (tid & 1) * 8;

    for (int ks = 0; ks < 8; ks++) {
        __syncthreads();
        {
            const float* hp = &h[(size_t)(row0 + hr) * 128 + ks * 16 + hk];
            float4 v0 = *(const float4*)hp;
            float4 v1 = *(const float4*)(hp + 4);
            float v[8] = {v0.x, v0.y, v0.z, v0.w, v1.x, v1.y, v1.z, v1.w};
            u32 hh[4], ll[4];
#pragma unroll
            for (int e = 0; e < 4; e++) {
                __nv_bfloat162 hp2 = __floats2bfloat162_rn(v[2*e], v[2*e+1]);
                float l0 = v[2*e]   - __bfloat162float(hp2.x);
                float l1 = v[2*e+1] - __bfloat162float(hp2.y);
                __nv_bfloat162 lp2 = __floats2bfloat162_rn(l0, l1);
                hh[e] = *(u32*)&hp2;
                ll[e] = *(u32*)&lp2;
            }
            *(uint4*)(hs_hi + hr * HSP + hk * 2) = *(uint4*)hh;
            *(uint4*)(hs_lo + hr * HSP + hk * 2) = *(uint4*)ll;
        }
        __syncthreads();
        u32 ahi[4], alo[4];
        LDSM4(ahi, adAhi);
        LDSM4(alo, adAlo);
#pragma unroll
        for (int p = 0; p < 8; p++) {
            u32 bhi[4], blo[4];
            LDSM4(bhi, adBhi + p * (16 * WTP) + ks * 32);
            LDSM4(blo, adBlo + p * (16 * WTP) + ks * 32);
            mma_bf16(acc[2 * p],     ahi, bhi);
            mma_bf16(acc[2 * p],     ahi, blo);
            mma_bf16(acc[2 * p],     alo, bhi);
            mma_bf16(acc[2 * p + 1], ahi, bhi + 2);
            mma_bf16(acc[2 * p + 1], ahi, blo + 2);
            mma_bf16(acc[2 * p + 1], alo, bhi + 2);
        }
    }
    __syncthreads();

    const int cb = 2 * (lane & 3);
    const int ia = wp * 16 + (lane >> 2);
    {
        float sa = 0.f, sb = 0.f, da = 0.f, db = 0.f;
#pragma unroll
        for (int nf = 0; nf < 16; nf++) {
            int c = nf * 8 + cb;
            float a0 = aT[c], a1 = aT[c + 1];
            float b0 = aT[128 + c], b1 = aT[128 + c + 1];
            sa += acc[nf][0] * a0 + acc[nf][1] * a1;
            da += acc[nf][0] * b0 + acc[nf][1] * b1;
            sb += acc[nf][2] * a0 + acc[nf][3] * a1;
            db += acc[nf][2] * b0 + acc[nf][3] * b1;
        }
#pragma unroll
        for (int off = 1; off <= 2; off <<= 1) {
            sa += __shfl_xor_sync(0xffffffffu, sa, off);
            sb += __shfl_xor_sync(0xffffffffu, sb, off);
            da += __shfl_xor_sync(0xffffffffu, da, off);
            db += __shfl_xor_sync(0xffffffffu, db, off);
        }
        if ((lane & 3) == 0) {
            sredS[ia] = sa;     dredS[ia] = da;
            sredS[ia + 8] = sb; dredS[ia + 8] = db;
        }
    }

#pragma unroll
    for (int nf = 0; nf < 16; nf++) {
        int c = nf * 8 + cb;
        __nv_bfloat162 hA = __floats2bfloat162_rn(acc[nf][0], acc[nf][1]);
        __nv_bfloat162 lA = __floats2bfloat162_rn(
            acc[nf][0] - __bfloat162float(hA.x),
            acc[nf][1] - __bfloat162float(hA.y));
        __nv_bfloat162 hB = __floats2bfloat162_rn(acc[nf][2], acc[nf][3]);
        __nv_bfloat162 lB = __floats2bfloat162_rn(
            acc[nf][2] - __bfloat162float(hB.x),
            acc[nf][3] - __bfloat162float(hB.y));
        *(u32*)(tb0 + ia * TBPB + c * 2)       = *(u32*)&hA;
        *(u32*)(tb1 + ia * TBPB + c * 2)       = *(u32*)&lA;
        *(u32*)(tb0 + (ia + 8) * TBPB + c * 2) = *(u32*)&hB;
        *(u32*)(tb1 + (ia + 8) * TBPB + c * 2) = *(u32*)&lB;
    }
    __syncthreads();

    if (tid < 128) {
        int n = row0 + tid;
        float s = sredS[tid], dd = dredS[tid];
        g_es[n] = s;  g_ed[n] = dd;
        g_F[n] = expf(s);         g_f[n] = expf(0.2f * s);
        g_G[n] = expf(dd);        g_g[n] = expf(0.2f * dd);
    }

    {
        const int bts = row0 >> 9;
        const int jc0 = row0 & 511;
        const int dr  = tid >> 1;
        const int jb  = (tid & 1) * 64;
        size_t gbase = ((size_t)bts * 128 + dr) * 512 + jc0 + jb;
#pragma unroll
        for (int buf = 0; buf < 2; buf++) {
            __nv_bfloat16* gdst = buf ? g_WhT_lo : g_WhT_hi;
            const char* src = buf ? tb1 : tb0;
#pragma unroll
            for (int q = 0; q < 8; q++) {
                u16 w[8];
#pragma unroll
                for (int e = 0; e < 8; e++)
                    w[e] = *(const u16*)(src + (jb + q * 8 + e) * TBPB + dr * 2);
                *(uint4*)&gdst[gbase + q * 8] = *(uint4*)w;
            }
        }
    }
}

// ---------------------------------------------------------------------------
// Kernel 2: adjacency -> bitmask
// ---------------------------------------------------------------------------
__global__ __launch_bounds__(256) void k_adjbits(const int* __restrict__ adj) {
    int idx = blockIdx.x * 256 + threadIdx.x;
    int i = idx >> 4, w = idx & 15;
    unsigned bits = 0;
#pragma unroll
    for (int b = 0; b < 32; b++)
        if (adj[i * NN + w * 32 + b] > 0) bits |= (1u << b);
    g_adjbits[idx] = bits;
}

// ---------------------------------------------------------------------------
// Kernel 3: tensor-core fused masked-softmax-attention, 64-i tiles for
// 2 CTAs/SM (reg/smem halved vs R16). Block = (bt, 64-row i-tile).
// D[d][i] = sum_j WhT[d][j]*C[i][j]; out[i][d] = D[d][i]/den[i]
// Dynamic smem: A 2x18432 + C 2x9216 = 55296 B.
// ---------------------------------------------------------------------------
#define PITCH_B 144                      // 72 bf16 per row
__global__ __launch_bounds__(256, 2) void k_attn(float* __restrict__ out) {
    extern __shared__ char dyn[];
    char* smA_hi = dyn;                  // [128 d][72] bf16 = 18432 B
    char* smA_lo = dyn + 18432;
    char* smB_hi = dyn + 36864;          // [64 i][72] bf16 = 9216 B
    char* smB_lo = dyn + 46080;          // total 55296 B

    __shared__ unsigned bitsS[64 * 16];
    __shared__ float edS[64], GS[64], gS[64];
    __shared__ float denS[256];
    __shared__ float invD[64];

    const int tid  = threadIdx.x;
    const int lane = tid & 31;
    const int wp   = tid >> 5;
    const int bt   = blockIdx.x >> 3;
    const int tile = blockIdx.x & 7;
    const int base = bt * NN;
    const int i0   = tile * 64;

    // adjacency preload: 64 rows x 16 words = 256 uint4, 1/thread
    {
        int r = tid >> 2, w4 = (tid & 3) * 4;
        *(uint4*)&bitsS[r * 16 + w4] = *(const uint4*)&g_adjbits[(i0 + r) * 16 + w4];
    }

    // phase-A identity: thread owns C row i (tid>>2), j-quarter q (16 j's)
    const int i = tid >> 2;
    const int q = tid & 3;
    const float esv = g_es[base + i0 + i];
    const float Fv  = g_F[base + i0 + i];
    const float fv  = g_f[base + i0 + i];
    float den = 0.f;

    const __nv_bfloat16* srcHi = g_WhT_hi + (size_t)bt * 128 * 512;
    const __nv_bfloat16* srcLo = g_WhT_lo + (size_t)bt * 128 * 512;

    const int arow  = (lane & 7) + ((lane >> 3) & 1) * 8;
    const int akoff = (lane >> 4) * 8;
    const int brow  = (lane & 7) + (lane >> 4) * 8;
    const int bkoff = ((lane >> 3) & 1) * 8;
    const u32 adAhi = smem_u32(smA_hi) + (wp * 16 + arow) * PITCH_B + akoff * 2;
    const u32 adAlo = smem_u32(smA_lo) + (wp * 16 + arow) * PITCH_B + akoff * 2;
    const u32 adBhi = smem_u32(smB_hi) + brow * PITCH_B + bkoff * 2;
    const u32 adBlo = smem_u32(smB_lo) + brow * PITCH_B + bkoff * 2;

    float acc[8][4];
#pragma unroll
    for (int nf = 0; nf < 8; nf++)
#pragma unroll
        for (int qq = 0; qq < 4; qq++) acc[nf][qq] = 0.f;

    for (int ch = 0; ch < 8; ch++) {
        const int j0 = ch * 64;
        __syncthreads();                 // prior MMA reads done
        // stage exp tables + A tiles (WhT hi/lo)
        if (tid < 64)       edS[tid]      = g_ed[base + j0 + tid];
        else if (tid < 128) GS[tid - 64]  = g_G[base + j0 + tid - 64];
        else if (tid < 192) gS[tid - 128] = g_g[base + j0 + tid - 128];
        {
            const int slot = tid & 7;            // 8 bf16 (16 B)
            const int drow = tid >> 3;           // 32 d-rows per pass
#pragma unroll
            for (int it = 0; it < 4; it++) {
                int d = drow + it * 32;
                size_t off = (size_t)d * 512 + j0 + slot * 8;
                *(uint4*)(smA_hi + d * PITCH_B + slot * 16) = *(const uint4*)(srcHi + off);
                *(uint4*)(smA_lo + d * PITCH_B + slot * 16) = *(const uint4*)(srcLo + off);
            }
        }
        __syncthreads();
        // phase A: C tile row i, 16 j's (hi/lo bf16 pairs)
        {
            unsigned bits = bitsS[i * 16 + ch * 2 + (q >> 1)] >> ((q & 1) * 16);
#pragma unroll
            for (int jj = 0; jj < 16; jj += 2) {
                int j = q * 16 + jj;
                float c0 = 0.f, c1 = 0.f;
                if ((bits >> jj) & 1u) {
                    float t = esv + edS[j];
                    c0 = (t > 0.f) ? Fv * GS[j] : fv * gS[j];
                }
                if ((bits >> (jj + 1)) & 1u) {
                    float t = esv + edS[j + 1];
                    c1 = (t > 0.f) ? Fv * GS[j + 1] : fv * gS[j + 1];
                }
                den += c0 + c1;
                __nv_bfloat162 hp = __floats2bfloat162_rn(c0, c1);
                float l0 = c0 - __bfloat162float(hp.x);
                float l1 = c1 - __bfloat162float(hp.y);
                __nv_bfloat162 lp = __floats2bfloat162_rn(l0, l1);
                *(u32*)(smB_hi + i * PITCH_B + j * 2) = *(u32*)&hp;
                *(u32*)(smB_lo + i * PITCH_B + j * 2) = *(u32*)&lp;
            }
        }
        __syncthreads();
        // MMA: 4 k-steps x 4 n-frag-pairs x {hh, hl, lh}
#pragma unroll
        for (int ks = 0; ks < 4; ks++) {
            u32 ahi[4], alo[4];
            LDSM4(ahi, adAhi + ks * 32);
            LDSM4(alo, adAlo + ks * 32);
#pragma unroll
            for (int p = 0; p < 4; p++) {
                u32 bhi[4], blo[4];
                LDSM4(bhi, adBhi + p * (16 * PITCH_B) + ks * 32);
                LDSM4(blo, adBlo + p * (16 * PITCH_B) + ks * 32);
                mma_bf16(acc[2 * p],     ahi, bhi);
                mma_bf16(acc[2 * p],     ahi, blo);
                mma_bf16(acc[2 * p],     alo, bhi);
                mma_bf16(acc[2 * p + 1], ahi, bhi + 2);
                mma_bf16(acc[2 * p + 1], ahi, blo + 2);
                mma_bf16(acc[2 * p + 1], alo, bhi + 2);
            }
        }
    }

    denS[tid] = den;
    __syncthreads();
    if (tid < 64)
        invD[tid] = 1.0f / (denS[4 * tid] + denS[4 * tid + 1]
                          + denS[4 * tid + 2] + denS[4 * tid + 3]);
    __syncthreads();

    // epilogue: lane l frag nf -> D[d][i]: d = wp*16 + l/4 (+8), i = nf*8+2(l&3)
    {
        const int dl = wp * 16 + (lane >> 2);
        const int il = 2 * (lane & 3);
#pragma unroll
        for (int nf = 0; nf < 8; nf++) {
            int ir = nf * 8 + il;
            float v0 = invD[ir], v1 = invD[ir + 1];
            float* p0 = out + (size_t)(base + i0 + ir) * 128 + dl;
            p0[0]        = acc[nf][0] * v0;
            p0[128]      = acc[nf][1] * v1;
            p0[8]        = acc[nf][2] * v0;
            p0[128 + 8]  = acc[nf][3] * v1;
        }
    }
}

// ---------------------------------------------------------------------------
extern "C" void kernel_launch(void* const* d_in, const int* in_sizes, int n_in,
                              void* d_out, int out_size) {
    const float* h   = (const float*)d_in[0];   // (4,32,512,128) f32
    const int*   adj = (const int*)d_in[1];     // (512,512) i32
    const float* W   = (const float*)d_in[2];   // (128,128) f32
    const float* a   = (const float*)d_in[3];   // (256,) f32
    float* out = (float*)d_out;                 // (4,32,512,128) f32

    const int gemm_smem = 81920;                // WT + hs (tb aliases)
    const int attn_smem = 55296;                // A(2x18432) + C(2x9216)
    cudaFuncSetAttribute(k_gemm, cudaFuncAttributeMaxDynamicSharedMemorySize,
                         gemm_smem);
    cudaFuncSetAttribute(k_attn, cudaFuncAttributeMaxDynamicSharedMemorySize,
                         attn_smem);

    k_prepW<<<1, 256>>>(W);                         // W^T bf16 hi/lo
    k_gemm<<<NROWS / 128, 256, gemm_smem>>>(h, a);  // Wh^T + exp tables (mma)
    k_adjbits<<<(NN * 16) / 256, 256>>>(adj);       // adj bitmask
    k_attn<<<BT * 8, 256, attn_smem>>>(out);        // mma.sync softmax-attn
}